// round 2
// baseline (speedup 1.0000x reference)
#include <cuda_runtime.h>
#include <cstdint>

// ROI adaptive average pooling via shared-memory crop staging.
// x:    [B=8, C=64, H=256, W=256] fp32
// rois: [B=8, S=128, 5] int32 (idx, x1, y1, x2, y2); roi sides in [8,40]
// out:  [B, S*C, 7, 7] fp32; torch adaptive-pool integer bin bounds.
//
// One block per (b,s). Channels processed in chunks of NC=4:
//   1) warps cooperatively load the NC crop tiles into smem (coalesced rows)
//   2) threads compute one bin each from smem
// This removes the warp-divergent global loads of the direct kernel (the L1
// wavefront bottleneck) and replaces them with dense coalesced LDG + LDS.

namespace {
constexpr int B  = 8;
constexpr int C  = 64;
constexpr int H  = 256;
constexpr int W  = 256;
constexpr int S  = 128;
constexpr int OH = 7;
constexpr int OW = 7;

constexpr int NC    = 4;        // channels staged per chunk
constexpr int MAXD  = 40;       // max roi side
constexpr int PITCH = MAXD + 1; // pad to 41 floats: y-stride 41 mod 32 = 9 (conflict-free-ish)
constexpr int NCHUNK = C / NC;  // 16
constexpr int THREADS = 256;
constexpr int NWARPS  = THREADS / 32;
}

__global__ void __launch_bounds__(THREADS) roi_pool_smem_kernel(
    const float* __restrict__ x,
    const int*   __restrict__ rois,
    float*       __restrict__ out)
{
    __shared__ float tile[NC][MAXD][PITCH];   // 4*40*41*4 = 26240 B

    const int bs = blockIdx.x;       // b*S + s
    const int b  = bs / S;

    const int* r = rois + bs * 5;
    const int x1 = r[1];
    const int y1 = r[2];
    const int ww = r[3] - x1;        // [8,40]
    const int hh = r[4] - y1;        // [8,40]

    const int tid  = threadIdx.x;
    const int lane = tid & 31;
    const int warp = tid >> 5;

    // per-thread bin assignment for compute phase (two passes of 196 bins)
    // t = cl*49 + oy*7 + ox
    for (int chunk = 0; chunk < NCHUNK; ++chunk) {
        // ---- load phase: NC crops, coalesced row loads ----
        #pragma unroll
        for (int cl = 0; cl < NC; ++cl) {
            const float* src0 = x + ((size_t)(b * C + chunk * NC + cl) * H + y1) * W + x1;
            for (int y = warp; y < hh; y += NWARPS) {
                const float* srow = src0 + y * W;
                float* drow = &tile[cl][y][0];
                for (int xx = lane; xx < ww; xx += 32)
                    drow[xx] = __ldg(srow + xx);
            }
        }
        __syncthreads();

        // ---- compute phase: one bin per thread ----
        for (int t = tid; t < NC * OH * OW; t += THREADS) {
            const int ox = t % OW;
            const int tt = t / OW;
            const int oy = tt % OH;
            const int cl = tt / OH;

            const int sy = (oy * hh) / OH;
            const int ey = ((oy + 1) * hh + (OH - 1)) / OH;
            const int sx = (ox * ww) / OW;
            const int ex = ((ox + 1) * ww + (OW - 1)) / OW;

            float acc = 0.0f;
            for (int yy = sy; yy < ey; ++yy) {
                const float* trow = &tile[cl][yy][0];
                #pragma unroll 4
                for (int xx = sx; xx < ex; ++xx)
                    acc += trow[xx];
            }

            const int c = chunk * NC + cl;
            out[((size_t)bs * C + c) * (OH * OW) + oy * OW + ox] =
                acc / (float)((ey - sy) * (ex - sx));
        }
        __syncthreads();   // protect tile before next chunk overwrites it
    }
}

extern "C" void kernel_launch(void* const* d_in, const int* in_sizes, int n_in,
                              void* d_out, int out_size)
{
    const float* x    = (const float*)d_in[0];
    const int*   rois = (const int*)d_in[1];
    float*       out  = (float*)d_out;

    roi_pool_smem_kernel<<<B * S, THREADS>>>(x, rois, out);
}

// round 3
// speedup vs baseline: 3.2927x; 3.2927x over previous
#include <cuda_runtime.h>
#include <cstdint>

// ROI adaptive average pooling: one WARP per (b, s, c) task.
// x:    [B=8, C=64, H=256, W=256] fp32
// rois: [B=8, S=128, 5] int32 (idx, x1, y1, x2, y2); roi sides in [8,40]
// out:  [B, S*C, 7, 7] fp32; torch adaptive-pool integer bin bounds.
//
// Phase 1 (registers): for each of the 7 row bands, the warp streams the
//   band's rows with coalesced loads (lane -> column lane / lane+32) and
//   accumulates per-column sums. Bands may share boundary rows (torch ceil
//   bound) -- each band loads its own full row range (L1 hits on overlap).
// Phase 2 (per-warp smem strip): column sums -> 49 bin window sums, one or
//   two bins per lane, coalesced 49-float store per warp. __syncwarp only.

namespace {
constexpr int B  = 8;
constexpr int C  = 64;
constexpr int H  = 256;
constexpr int W  = 256;
constexpr int S  = 128;
constexpr int OH = 7;
constexpr int OW = 7;
constexpr int MAXD = 40;

constexpr int WARPS_PER_BLOCK = 8;
constexpr int THREADS = WARPS_PER_BLOCK * 32;
constexpr int NTASK = B * S * C;                    // 65536 warp tasks
constexpr int NBLOCK = NTASK / WARPS_PER_BLOCK;     // 8192
}

__global__ void __launch_bounds__(THREADS) roi_pool_warp_kernel(
    const float* __restrict__ x,
    const int*   __restrict__ rois,
    float*       __restrict__ out)
{
    __shared__ float cs_all[WARPS_PER_BLOCK][OH][MAXD];  // 8*7*40*4 = 8960 B

    const int lane = threadIdx.x & 31;
    const int warp = threadIdx.x >> 5;

    const int task = blockIdx.x * WARPS_PER_BLOCK + warp;
    const int c  = task & (C - 1);
    const int bs = task >> 6;            // b*S + s
    const int b  = bs >> 7;              // bs / S

    const int* r = rois + bs * 5;
    const int x1 = r[1];
    const int y1 = r[2];
    const int w  = r[3] - x1;            // [8,40]
    const int h  = r[4] - y1;            // [8,40]

    const float* base = x + ((size_t)(b * C + c) * H) * W;

    const bool l0 = (lane      < w);
    const bool l1 = (lane + 32 < w);

    float (*cs)[MAXD] = cs_all[warp];

    // ---- phase 1: per-band column sums (registers -> smem strip) ----
    #pragma unroll
    for (int oy = 0; oy < OH; ++oy) {
        const int ys = y1 + (oy * h) / OH;
        const int ye = y1 + ((oy + 1) * h + (OH - 1)) / OH;

        float a0 = 0.0f, a1 = 0.0f;
        const float* p = base + (size_t)ys * W + x1;
        for (int y = ys; y < ye; ++y, p += W) {
            if (l0) a0 += __ldg(p + lane);
            if (l1) a1 += __ldg(p + lane + 32);
        }
        if (l0) cs[oy][lane] = a0;
        if (l1) cs[oy][lane + 32] = a1;
    }
    __syncwarp();

    // ---- phase 2: bins from column sums ----
    float* obase = out + (size_t)task * (OH * OW);
    #pragma unroll
    for (int t = lane; t < OH * OW; t += 32) {
        const int oy = t / OW;
        const int ox = t - oy * OW;

        const int sx = (ox * w) / OW;
        const int ex = ((ox + 1) * w + (OW - 1)) / OW;
        const int sy = (oy * h) / OH;
        const int ey = ((oy + 1) * h + (OH - 1)) / OH;

        float acc = 0.0f;
        #pragma unroll 4
        for (int xx = sx; xx < ex; ++xx)
            acc += cs[oy][xx];

        obase[t] = acc / (float)((ey - sy) * (ex - sx));
    }
}

extern "C" void kernel_launch(void* const* d_in, const int* in_sizes, int n_in,
                              void* d_out, int out_size)
{
    const float* x    = (const float*)d_in[0];
    const int*   rois = (const int*)d_in[1];
    float*       out  = (float*)d_out;

    roi_pool_warp_kernel<<<NBLOCK, THREADS>>>(x, rois, out);
}

// round 4
// speedup vs baseline: 3.3207x; 1.0085x over previous
#include <cuda_runtime.h>
#include <cstdint>

// ROI adaptive average pooling: one WARP per (b, s, channel-group-of-4).
// x:    [B=8, C=64, H=256, W=256] fp32
// rois: [B=8, S=128, 5] int32 (idx, x1, y1, x2, y2); roi sides in [8,40]
// out:  [B, S*C, 7, 7] fp32; torch adaptive-pool integer bin bounds.
//
// All channels of a (b,s) share roi geometry -> one address stream feeds 4
// channel loads (stride H*W), amortizing loop/bound/task overhead 4x.
// Narrow rois (w<=32, ~76% of cases) take a branch that never issues the
// second (lane+32) load set.

namespace {
constexpr int B  = 8;
constexpr int C  = 64;
constexpr int H  = 256;
constexpr int W  = 256;
constexpr int S  = 128;
constexpr int OH = 7;
constexpr int OW = 7;
constexpr int MAXD = 40;
constexpr int CH = H * W;                 // channel stride in elements

constexpr int NCH = 4;                    // channels per warp
constexpr int WPB = 4;                    // warps per block
constexpr int THREADS = WPB * 32;
constexpr int NTASK = B * S * (C / NCH);  // 16384 warp tasks
constexpr int NBLOCK = NTASK / WPB;       // 4096
}

__global__ void __launch_bounds__(THREADS) roi_pool_warp4_kernel(
    const float* __restrict__ x,
    const int*   __restrict__ rois,
    float*       __restrict__ out)
{
    __shared__ float cs_all[WPB][NCH][OH][MAXD];   // 4*4*7*40*4 = 17920 B

    const int lane = threadIdx.x & 31;
    const int warp = threadIdx.x >> 5;

    const int task = blockIdx.x * WPB + warp;      // [0, 16384)
    const int cg   = task & (C / NCH - 1);         // channel group [0,16)
    const int bs   = task >> 4;                    // b*S + s
    const int b    = bs >> 7;
    const int c0   = cg * NCH;

    const int* r = rois + bs * 5;
    const int x1 = r[1];
    const int y1 = r[2];
    const int w  = r[3] - x1;                      // [8,40]
    const int h  = r[4] - y1;                      // [8,40]

    const float* chan0 = x + (size_t)(b * C + c0) * CH;

    float (*cs)[OH][MAXD] = cs_all[warp];

    // ---- phase 1: per-band column sums for 4 channels ----
    if (w <= 32) {
        const bool act = (lane < w);
        #pragma unroll
        for (int oy = 0; oy < OH; ++oy) {
            const int ys = y1 + (oy * h) / OH;
            const int ye = y1 + ((oy + 1) * h + (OH - 1)) / OH;

            float a0 = 0.f, a1 = 0.f, a2 = 0.f, a3 = 0.f;
            const float* p = chan0 + (size_t)ys * W + x1 + lane;
            for (int y = ys; y < ye; ++y, p += W) {
                if (act) {
                    a0 += __ldg(p);
                    a1 += __ldg(p + CH);
                    a2 += __ldg(p + 2 * CH);
                    a3 += __ldg(p + 3 * CH);
                }
            }
            if (act) {
                cs[0][oy][lane] = a0;
                cs[1][oy][lane] = a1;
                cs[2][oy][lane] = a2;
                cs[3][oy][lane] = a3;
            }
        }
    } else {
        const bool act1 = (lane + 32 < w);   // lane always < 32 < w here
        #pragma unroll
        for (int oy = 0; oy < OH; ++oy) {
            const int ys = y1 + (oy * h) / OH;
            const int ye = y1 + ((oy + 1) * h + (OH - 1)) / OH;

            float a0 = 0.f, a1 = 0.f, a2 = 0.f, a3 = 0.f;
            float b0 = 0.f, b1 = 0.f, b2 = 0.f, b3 = 0.f;
            const float* p = chan0 + (size_t)ys * W + x1 + lane;
            for (int y = ys; y < ye; ++y, p += W) {
                a0 += __ldg(p);
                a1 += __ldg(p + CH);
                a2 += __ldg(p + 2 * CH);
                a3 += __ldg(p + 3 * CH);
                if (act1) {
                    b0 += __ldg(p + 32);
                    b1 += __ldg(p + CH + 32);
                    b2 += __ldg(p + 2 * CH + 32);
                    b3 += __ldg(p + 3 * CH + 32);
                }
            }
            cs[0][oy][lane] = a0;
            cs[1][oy][lane] = a1;
            cs[2][oy][lane] = a2;
            cs[3][oy][lane] = a3;
            if (act1) {
                cs[0][oy][lane + 32] = b0;
                cs[1][oy][lane + 32] = b1;
                cs[2][oy][lane + 32] = b2;
                cs[3][oy][lane + 32] = b3;
            }
        }
    }
    __syncwarp();

    // ---- phase 2: bins from column sums, 4 channels per lane-task ----
    float* obase = out + (size_t)(bs * C + c0) * (OH * OW);
    for (int t = lane; t < OH * OW; t += 32) {
        const int oy = t / OW;
        const int ox = t - oy * OW;

        const int sx = (ox * w) / OW;
        const int ex = ((ox + 1) * w + (OW - 1)) / OW;
        const int sy = (oy * h) / OH;
        const int ey = ((oy + 1) * h + (OH - 1)) / OH;

        float s0 = 0.f, s1 = 0.f, s2 = 0.f, s3 = 0.f;
        #pragma unroll 4
        for (int xx = sx; xx < ex; ++xx) {
            s0 += cs[0][oy][xx];
            s1 += cs[1][oy][xx];
            s2 += cs[2][oy][xx];
            s3 += cs[3][oy][xx];
        }

        const float inv = 1.0f / (float)((ey - sy) * (ex - sx));
        obase[t]                  = s0 * inv;
        obase[t +     OH * OW]    = s1 * inv;
        obase[t + 2 * OH * OW]    = s2 * inv;
        obase[t + 3 * OH * OW]    = s3 * inv;
    }
}

extern "C" void kernel_launch(void* const* d_in, const int* in_sizes, int n_in,
                              void* d_out, int out_size)
{
    const float* x    = (const float*)d_in[0];
    const int*   rois = (const int*)d_in[1];
    float*       out  = (float*)d_out;

    roi_pool_warp4_kernel<<<NBLOCK, THREADS>>>(x, rois, out);
}

// round 5
// speedup vs baseline: 4.8523x; 1.4613x over previous
#include <cuda_runtime.h>
#include <cstdint>

// ROI adaptive average pooling: one WARP per (b, s, channel-group-of-4),
// single pass over roi rows with incremental band tracking.
// x:    [B=8, C=64, H=256, W=256] fp32
// rois: [B=8, S=128, 5] int32 (idx, x1, y1, x2, y2); roi sides in [8,40]
// out:  [B, S*C, 7, 7] fp32; torch adaptive-pool integer bin bounds.
//
// Phase 1: stream the h roi rows once (unrolled x4/x2, predicated loads so
//   all LDGs of a group issue before any FADD -> high MLP). Row r feeds band
//   cur; on r == eyc (band end) flush accumulators to the smem column-sum
//   strip; boundary rows that straddle two bands (r >= syn) are carried into
//   the next band's accumulator. All band control is warp-uniform.
// Phase 2: bins from column sums (as R4), coalesced stores.

namespace {
constexpr int B  = 8;
constexpr int C  = 64;
constexpr int H  = 256;
constexpr int W  = 256;
constexpr int S  = 128;
constexpr int OH = 7;
constexpr int OW = 7;
constexpr int MAXD = 40;
constexpr int CH = H * W;

constexpr int NCH = 4;                    // channels per warp
constexpr int WPB = 8;                    // warps per block
constexpr int THREADS = WPB * 32;
constexpr int NTASK = B * S * (C / NCH);  // 16384
constexpr int NBLOCK = NTASK / WPB;       // 2048
}

__global__ void __launch_bounds__(THREADS) roi_pool_scan_kernel(
    const float* __restrict__ x,
    const int*   __restrict__ rois,
    float*       __restrict__ out)
{
    __shared__ float cs_all[WPB][NCH][OH][MAXD];   // 8*4*7*40*4 = 35840 B

    const int lane = threadIdx.x & 31;
    const int warp = threadIdx.x >> 5;

    const int task = blockIdx.x * WPB + warp;
    const int cg   = task & (C / NCH - 1);
    const int bs   = task >> 4;
    const int b    = bs >> 7;
    const int c0   = cg * NCH;

    const int* r = rois + bs * 5;
    const int x1 = r[1];
    const int y1 = r[2];
    const int w  = r[3] - x1;              // [8,40]
    const int h  = r[4] - y1;              // [8,40]

    const float* p0 = x + (size_t)(b * C + c0) * CH + (size_t)y1 * W + x1;

    float (*cs)[OH][MAXD] = cs_all[warp];

    if (w <= 32) {
        // ---------------- narrow path: one lane-set, unroll 4 ----------------
        const bool act = (lane < w);
        float a0 = 0.f, a1 = 0.f, a2 = 0.f, a3 = 0.f;       // current band acc
        float s0 = 0.f, s1 = 0.f, s2 = 0.f, s3 = 0.f;       // straddle carry
        int cur = 0;
        int eyc = (h + 6) / 7;                               // ceil((cur+1)h/7)
        int syn = h / 7;                                     // floor((cur+1)h/7)

        for (int r0 = 0; r0 < h; r0 += 4) {
            float v[4][NCH];
            #pragma unroll
            for (int i = 0; i < 4; ++i) {
                const float* p = p0 + (size_t)(r0 + i) * W + lane;
                const bool pv = act && (r0 + i < h);
                v[i][0] = pv ? __ldg(p)          : 0.f;
                v[i][1] = pv ? __ldg(p + CH)     : 0.f;
                v[i][2] = pv ? __ldg(p + 2 * CH) : 0.f;
                v[i][3] = pv ? __ldg(p + 3 * CH) : 0.f;
            }
            #pragma unroll
            for (int i = 0; i < 4; ++i) {
                const int rr = r0 + i;
                if (rr < h) {                                // warp-uniform
                    if (rr == eyc) {                         // band transition
                        if (act) {
                            cs[0][cur][lane] = a0;
                            cs[1][cur][lane] = a1;
                            cs[2][cur][lane] = a2;
                            cs[3][cur][lane] = a3;
                        }
                        a0 = s0; a1 = s1; a2 = s2; a3 = s3;
                        ++cur;
                        eyc = ((cur + 1) * h + 6) / 7;
                        syn = ((cur + 1) * h) / 7;
                    }
                    const bool sd = (rr >= syn);             // straddle row
                    s0 = sd ? v[i][0] : 0.f;
                    s1 = sd ? v[i][1] : 0.f;
                    s2 = sd ? v[i][2] : 0.f;
                    s3 = sd ? v[i][3] : 0.f;
                    a0 += v[i][0];
                    a1 += v[i][1];
                    a2 += v[i][2];
                    a3 += v[i][3];
                }
            }
        }
        if (act) {                                           // cur == 6 here
            cs[0][cur][lane] = a0;
            cs[1][cur][lane] = a1;
            cs[2][cur][lane] = a2;
            cs[3][cur][lane] = a3;
        }
    } else {
        // ---------------- wide path (w in 33..40): two lane-sets, unroll 2 ----------------
        const bool act1 = (lane + 32 < w);
        float a0 = 0.f, a1 = 0.f, a2 = 0.f, a3 = 0.f;
        float b0 = 0.f, b1 = 0.f, b2 = 0.f, b3 = 0.f;
        float sa0 = 0.f, sa1 = 0.f, sa2 = 0.f, sa3 = 0.f;
        float sb0 = 0.f, sb1 = 0.f, sb2 = 0.f, sb3 = 0.f;
        int cur = 0;
        int eyc = (h + 6) / 7;
        int syn = h / 7;

        for (int r0 = 0; r0 < h; r0 += 2) {
            float va[2][NCH], vb[2][NCH];
            #pragma unroll
            for (int i = 0; i < 2; ++i) {
                const float* p = p0 + (size_t)(r0 + i) * W + lane;
                const bool pv  = (r0 + i < h);
                const bool pv1 = pv && act1;
                va[i][0] = pv  ? __ldg(p)               : 0.f;
                va[i][1] = pv  ? __ldg(p + CH)          : 0.f;
                va[i][2] = pv  ? __ldg(p + 2 * CH)      : 0.f;
                va[i][3] = pv  ? __ldg(p + 3 * CH)      : 0.f;
                vb[i][0] = pv1 ? __ldg(p + 32)          : 0.f;
                vb[i][1] = pv1 ? __ldg(p + CH + 32)     : 0.f;
                vb[i][2] = pv1 ? __ldg(p + 2 * CH + 32) : 0.f;
                vb[i][3] = pv1 ? __ldg(p + 3 * CH + 32) : 0.f;
            }
            #pragma unroll
            for (int i = 0; i < 2; ++i) {
                const int rr = r0 + i;
                if (rr < h) {
                    if (rr == eyc) {
                        cs[0][cur][lane] = a0;
                        cs[1][cur][lane] = a1;
                        cs[2][cur][lane] = a2;
                        cs[3][cur][lane] = a3;
                        if (act1) {
                            cs[0][cur][lane + 32] = b0;
                            cs[1][cur][lane + 32] = b1;
                            cs[2][cur][lane + 32] = b2;
                            cs[3][cur][lane + 32] = b3;
                        }
                        a0 = sa0; a1 = sa1; a2 = sa2; a3 = sa3;
                        b0 = sb0; b1 = sb1; b2 = sb2; b3 = sb3;
                        ++cur;
                        eyc = ((cur + 1) * h + 6) / 7;
                        syn = ((cur + 1) * h) / 7;
                    }
                    const bool sd = (rr >= syn);
                    sa0 = sd ? va[i][0] : 0.f;
                    sa1 = sd ? va[i][1] : 0.f;
                    sa2 = sd ? va[i][2] : 0.f;
                    sa3 = sd ? va[i][3] : 0.f;
                    sb0 = sd ? vb[i][0] : 0.f;
                    sb1 = sd ? vb[i][1] : 0.f;
                    sb2 = sd ? vb[i][2] : 0.f;
                    sb3 = sd ? vb[i][3] : 0.f;
                    a0 += va[i][0]; a1 += va[i][1]; a2 += va[i][2]; a3 += va[i][3];
                    b0 += vb[i][0]; b1 += vb[i][1]; b2 += vb[i][2]; b3 += vb[i][3];
                }
            }
        }
        cs[0][cur][lane] = a0;
        cs[1][cur][lane] = a1;
        cs[2][cur][lane] = a2;
        cs[3][cur][lane] = a3;
        if (act1) {
            cs[0][cur][lane + 32] = b0;
            cs[1][cur][lane + 32] = b1;
            cs[2][cur][lane + 32] = b2;
            cs[3][cur][lane + 32] = b3;
        }
    }
    __syncwarp();

    // ---- phase 2: bins from column sums, 4 channels per lane-task ----
    float* obase = out + (size_t)(bs * C + c0) * (OH * OW);
    for (int t = lane; t < OH * OW; t += 32) {
        const int oy = t / OW;
        const int ox = t - oy * OW;

        const int sx = (ox * w) / OW;
        const int ex = ((ox + 1) * w + (OW - 1)) / OW;
        const int sy = (oy * h) / OH;
        const int ey = ((oy + 1) * h + (OH - 1)) / OH;

        float q0 = 0.f, q1 = 0.f, q2 = 0.f, q3 = 0.f;
        #pragma unroll 4
        for (int xx = sx; xx < ex; ++xx) {
            q0 += cs[0][oy][xx];
            q1 += cs[1][oy][xx];
            q2 += cs[2][oy][xx];
            q3 += cs[3][oy][xx];
        }

        const float inv = 1.0f / (float)((ey - sy) * (ex - sx));
        obase[t]               = q0 * inv;
        obase[t +     OH * OW] = q1 * inv;
        obase[t + 2 * OH * OW] = q2 * inv;
        obase[t + 3 * OH * OW] = q3 * inv;
    }
}

extern "C" void kernel_launch(void* const* d_in, const int* in_sizes, int n_in,
                              void* d_out, int out_size)
{
    const float* x    = (const float*)d_in[0];
    const int*   rois = (const int*)d_in[1];
    float*       out  = (float*)d_out;

    roi_pool_scan_kernel<<<NBLOCK, THREADS>>>(x, rois, out);
}